// round 6
// baseline (speedup 1.0000x reference)
#include <cuda_runtime.h>
#include <cstdint>

typedef unsigned long long u64;

#define B_  16
#define N_  8192
#define C_  256
#define K_  4096

// Output layout (float32): [features][indices][adjacency][scores]
#define OFF_FEAT   ((size_t)0)
#define OFF_IDX    ((size_t)B_ * K_ * C_)
#define OFF_ADJ    (OFF_IDX + (size_t)B_ * K_)
#define OFF_SCORES (OFF_ADJ + (size_t)B_ * K_ * K_)

// Scratch (device globals; no allocation allowed)
__device__ __align__(16) unsigned short g_idx[B_ * K_];
__device__ int g_pos[B_ * N_];
__device__ __align__(16) u64 g_keys[B_ * N_];      // 1 MB sort scratch

// ---------------------------------------------------------------------------
// Bitonic convention: at stage (k, j), the lower element of a pair keeps the
// max iff (i & k)==0  => final order descending.  Composite key
// flipped_score<<16 | (8191-idx) breaks ties by ascending index (jax.lax.top_k).
// ---------------------------------------------------------------------------
__device__ __forceinline__ void ce_pair(u64 &lo, u64 &hi, bool desc) {
    u64 a = lo, b = hi;
    u64 mx = a > b ? a : b;
    u64 mn = a > b ? b : a;
    lo = desc ? mx : mn;
    hi = desc ? mn : mx;
}
__device__ __forceinline__ u64 shfl_ce(u64 v, int j, bool keepmax) {
    u64 o = __shfl_xor_sync(0xFFFFFFFFu, v, j);
    u64 mx = v > o ? v : o;
    u64 mn = v > o ? o : v;
    return keepmax ? mx : mn;
}
__device__ __forceinline__ void smem_ce(u64* s, int i, int m, bool desc) {
    u64 a = s[i], c = s[m];
    if ((a < c) == desc) { s[i] = c; s[m] = a; }
}

// ---------------------------------------------------------------------------
// K1: sort each 4096-half (k=2..4096). grid B*2, block 512, 8 u64/thread,
// 32KB smem. Builds keys from scores and clears g_pos.
// Blocked layout: i = wbase + e*32 + l, wbase = warp*256 (16 warps * 256).
// Register stages cover j<=128 (e-bits 32/64/128 + lane bits 16..1).
// ---------------------------------------------------------------------------
__global__ __launch_bounds__(512)
void sort4096_kernel(const float* __restrict__ scores)
{
    __shared__ u64 s[4096];
    const int b  = blockIdx.x >> 1;
    const int cb = (blockIdx.x & 1) << 12;          // batch-local half base
    const int t  = threadIdx.x;
    const int l  = t & 31;
    const int wbase = (t >> 5) << 8;                // warp*256
    const float* sc = scores + (size_t)b * N_;

    u64 v[8];
    #pragma unroll
    for (int e = 0; e < 8; e++) {
        int I = cb + wbase + e * 32 + l;
        unsigned u = __float_as_uint(sc[I]);
        u ^= (u & 0x80000000u) ? 0xFFFFFFFFu : 0x80000000u;
        v[e] = ((u64)u << 16) | (unsigned)(8191 - I);
        g_pos[b * N_ + cb + e * 512 + t] = -1;
    }

    // ---- register phase: k = 2..256 (256-elem blocked groups) ----
    #pragma unroll
    for (int k = 2; k <= 256; k <<= 1) {
        #pragma unroll
        for (int eb = 4; eb >= 1; eb >>= 1) {
            const int j = eb << 5;
            if (j < k) {
                #pragma unroll
                for (int e = 0; e < 8; e++)
                    if (!(e & eb)) {
                        bool desc = (((cb + wbase + e * 32) & k) == 0);
                        ce_pair(v[e], v[e | eb], desc);
                    }
            }
        }
        #pragma unroll
        for (int j = 16; j >= 1; j >>= 1) {
            if (j < k) {
                #pragma unroll
                for (int e = 0; e < 8; e++) {
                    bool desc = (((cb + wbase + e * 32 + l) & k) == 0);
                    v[e] = shfl_ce(v[e], j, desc == ((l & j) == 0));
                }
            }
        }
    }

    // ---- k = 512..4096: smem stages j>=256, register tail j<=128 ----
    #pragma unroll 1
    for (int k = 512; k <= 4096; k <<= 1) {
        #pragma unroll
        for (int e = 0; e < 8; e++) s[wbase + e * 32 + l] = v[e];
        __syncthreads();
        #pragma unroll 1
        for (int j = k >> 1; j >= 256; j >>= 1) {
            #pragma unroll
            for (int q = 0; q < 4; q++) {
                int p = t + q * 512;                       // 0..2047 pairs
                int i = ((p & ~(j - 1)) << 1) | (p & (j - 1));
                bool desc = (((cb + i) & k) == 0);
                smem_ce(s, i, i + j, desc);
            }
            __syncthreads();
        }
        #pragma unroll
        for (int e = 0; e < 8; e++) v[e] = s[wbase + e * 32 + l];
        __syncthreads();
        #pragma unroll
        for (int eb = 4; eb >= 1; eb >>= 1) {
            #pragma unroll
            for (int e = 0; e < 8; e++)
                if (!(e & eb)) {
                    bool desc = (((cb + wbase + e * 32) & k) == 0);
                    ce_pair(v[e], v[e | eb], desc);
                }
        }
        #pragma unroll
        for (int j = 16; j >= 1; j >>= 1) {
            #pragma unroll
            for (int e = 0; e < 8; e++) {
                bool desc = (((cb + wbase + e * 32 + l) & k) == 0);
                v[e] = shfl_ce(v[e], j, desc == ((l & j) == 0));
            }
        }
    }

    #pragma unroll
    for (int e = 0; e < 8; e++)
        g_keys[(size_t)b * N_ + cb + wbase + e * 32 + l] = v[e];
}

// ---------------------------------------------------------------------------
// K2: fused orbit (k=8192 stages j=4096..1024, registers) + window finalize
// (j=512..1) + emit.  grid B*4, block 1024.
// Thread t loads the stride-1024 orbit {t + m*1024}; after the register
// stages, v[w] equals the value at rank (w*1024 + t).  Each CTA keeps its
// window w = blockIdx&3, finishes it in smem/shuffles, and emits.
// ---------------------------------------------------------------------------
__global__ __launch_bounds__(1024)
void orbitfin_kernel(float* __restrict__ out_idxf,
                     float* __restrict__ out_scores)
{
    __shared__ u64 s[1024];
    const int b = blockIdx.x >> 2;
    const int w = blockIdx.x & 3;                     // rank window
    const int t = threadIdx.x;
    const int l = t & 31;
    const u64* gk = g_keys + (size_t)b * N_;

    // orbit: j=4096 (keep max), j=2048, j=1024 — top half only survives
    u64 v[8];
    #pragma unroll
    for (int m = 0; m < 8; m++) v[m] = gk[t + (m << 10)];
    #pragma unroll
    for (int m = 0; m < 4; m++) {
        u64 a = v[m], c = v[m + 4];
        v[m] = a > c ? a : c;
    }
    #pragma unroll
    for (int m = 0; m < 2; m++) ce_pair(v[m], v[m + 2], true);
    ce_pair(v[0], v[1], true);
    ce_pair(v[2], v[3], true);

    s[t] = v[w];
    __syncthreads();

    // finalize window: smem stages j=512..32 (512 active pair-threads)
    #pragma unroll
    for (int j = 512; j >= 32; j >>= 1) {
        if (t < 512) {
            int i = ((t & ~(j - 1)) << 1) | (t & (j - 1));
            smem_ce(s, i, i + j, true);
        }
        __syncthreads();
    }

    // shuffle tail j=16..1 (1 elem/thread) + emit
    u64 x = s[t];
    #pragma unroll
    for (int j = 16; j >= 1; j >>= 1)
        x = shfl_ce(x, j, (l & j) == 0);

    const int rank = (w << 10) + t;
    int idx = 8191 - (int)(x & 0xFFFF);
    unsigned ku = (unsigned)(x >> 16);
    unsigned orig = (ku & 0x80000000u) ? (ku ^ 0x80000000u) : ~ku;
    g_idx[b * K_ + rank] = (unsigned short)idx;
    out_idxf[(size_t)b * K_ + rank]   = (float)idx;
    out_scores[(size_t)b * K_ + rank] = __uint_as_float(orig);
    g_pos[b * N_ + idx] = rank;
}

// ---------------------------------------------------------------------------
// Combined gather: blocks [0,8192) stage one adjacency source row in SMEM and
// serve every batch containing it; blocks [8192,16384) gather features.
// Streaming hints keep L2 free for the hot 128KB g_idx.
// ---------------------------------------------------------------------------
__global__ __launch_bounds__(512)
void gather_kernel(const float* __restrict__ A,
                   const float4* __restrict__ feat,
                   float* __restrict__ out_adj,
                   float4* __restrict__ out_feat)
{
    __shared__ float row[N_];   // 32 KB (adj branch only)
    if (blockIdx.x < 8192) {
        const int r = blockIdx.x;
        const float4* src  = (const float4*)(A + (size_t)r * N_);
        float4*       rowv = (float4*)row;
        for (int t = threadIdx.x; t < N_ / 4; t += 512)
            rowv[t] = __ldcs(src + t);
        __syncthreads();

        #pragma unroll 1
        for (int b = 0; b < B_; ++b) {
            int i = g_pos[b * N_ + r];
            if (i < 0) continue;
            float4* obase = (float4*)(out_adj + ((size_t)b * K_ + i) * K_);
            const ushort4* idx4 = (const ushort4*)(g_idx + b * K_);
            for (int t = threadIdx.x; t < K_ / 4; t += 512) {
                ushort4 c = idx4[t];
                __stcs(obase + t,
                       make_float4(row[c.x], row[c.y], row[c.z], row[c.w]));
            }
        }
    } else {
        int o = (blockIdx.x - 8192) * 512 + threadIdx.x;   // 0..4194303
        int frow = o >> 6;                                  // C/4=64 f4/row
        int c    = o & 63;
        int b    = frow >> 12;                              // K rows/batch
        int r    = g_idx[frow];
        __stcs(out_feat + o,
               __ldcs(feat + ((size_t)(b << 13) + r) * 64 + c));
    }
}

// ---------------------------------------------------------------------------
extern "C" void kernel_launch(void* const* d_in, const int* in_sizes, int n_in,
                              void* d_out, int out_size)
{
    const float* scores = (const float*)d_in[0];   // (B, N)
    const float* feat   = (const float*)d_in[1];   // (B, N, C)
    const float* adj    = (const float*)d_in[2];   // (N, N)
    float* out = (float*)d_out;

    float* out_feat   = out + OFF_FEAT;
    float* out_idxf   = out + OFF_IDX;
    float* out_adj    = out + OFF_ADJ;
    float* out_scores = out + OFF_SCORES;

    sort4096_kernel<<<B_ * 2, 512>>>(scores);
    orbitfin_kernel<<<B_ * 4, 1024>>>(out_idxf, out_scores);

    gather_kernel<<<16384, 512>>>(adj, (const float4*)feat,
                                  out_adj, (float4*)out_feat);
}